// round 16
// baseline (speedup 1.0000x reference)
#include <cuda_runtime.h>

#define TPB   256
#define SST   10
#define SSITE (16*SST)
#define WST   10

__device__ __forceinline__ void cmac(float2& c, float2 a, float2 b) {
    c.x = fmaf(a.x,b.x,fmaf(-a.y,b.y,c.x)); c.y = fmaf(a.x,b.y,fmaf(a.y,b.x,c.y));
}
__device__ __forceinline__ void cmacc(float2& c, float2 a, float2 b) { // a*conj(b)
    c.x = fmaf(a.x,b.x,fmaf(a.y,b.y,c.x));  c.y = fmaf(a.y,b.x,fmaf(-a.x,b.y,c.y));
}
__device__ __forceinline__ float2 f2lo(float4 v){return make_float2(v.x,v.y);}
__device__ __forceinline__ float2 f2hi(float4 v){return make_float2(v.z,v.w);}

#define F2_TOTAL (18*SSITE + 288 + 18*64 + 8*64 + 5*160)
#define SMEM_BYTES (F2_TOTAL*8)

// single-warp L transfer; zf=1 inserts Z on the physical leg.
// NOTE: Lin/Lout deliberately NOT __restrict__ (R15 bug: in-place call under
// restrict let ptxas hoist loads over stores). Here they are also always
// distinct buffers (ping-pong) anyway.
__device__ __forceinline__ void ltrans(const float2* __restrict__ Am,
                                       const float2* Lin,
                                       float2* Lout,
                                       float2* __restrict__ Wsc, int lane, int zf)
{
    {   const int q = lane >> 1, h = lane & 1;
        const int s = q >> 3, b2 = q & 7;
        float2 a0={0,0},a1={0,0},a2={0,0},a3={0,0};
#pragma unroll
        for (int b1 = 0; b1 < 8; ++b1) {
            float2 lv = Lin[b1*8 + b2];
            const float4* Ar = (const float4*)(Am + (b1*2+s)*SST);
            float4 w0 = Ar[2*h], w1 = Ar[2*h+1];
            cmac(a0,lv,f2lo(w0)); cmac(a1,lv,f2hi(w0));
            cmac(a2,lv,f2lo(w1)); cmac(a3,lv,f2hi(w1));
        }
        const float sg = (s && zf) ? -1.f : 1.f;
        float2* wr = Wsc + q*WST + 4*h;
        wr[0]=make_float2(sg*a0.x,sg*a0.y); wr[1]=make_float2(sg*a1.x,sg*a1.y);
        wr[2]=make_float2(sg*a2.x,sg*a2.y); wr[3]=make_float2(sg*a3.x,sg*a3.y);
    }
    __syncwarp();
    {   const int g1 = lane >> 2, g2h = lane & 3;
#pragma unroll
        for (int hh = 0; hh < 2; ++hh) {
            const int g2 = g2h + 4*hh;
            float2 p0={0,0},p1={0,0};
#pragma unroll
            for (int q = 0; q < 16; q += 2) {
                const int r0 = ((q  )&7)*2 + ((q  )>>3);
                const int r1 = ((q+1)&7)*2 + ((q+1)>>3);
                cmacc(p0, Wsc[(q  )*WST + g1], Am[r0*SST + g2]);
                cmacc(p1, Wsc[(q+1)*WST + g1], Am[r1*SST + g2]);
            }
            Lout[g1*8+g2] = make_float2(p0.x+p1.x, p0.y+p1.y);
        }
    }
    __syncwarp();
}

__device__ __forceinline__ float dot64_re(const float2* L, const float2* R, int lane) {
    float2 l0=L[lane], r0=R[lane], l1=L[lane+32], r1=R[lane+32];
    float v = l0.x*r0.x - l0.y*r0.y + l1.x*r1.x - l1.y*r1.y;
#pragma unroll
    for (int o = 16; o > 0; o >>= 1) v += __shfl_xor_sync(0xffffffffu, v, o);
    return v;
}

__global__ void __launch_bounds__(TPB, 1) vqc_mps_kernel(
    const float* __restrict__ w, const int* __restrict__ x, float* __restrict__ out)
{
    extern __shared__ float2 sm[];
    float2* S0   = sm;
    float2* Ush  = S0 + 18*SSITE;
    float2* Rb   = Ush + 288;
    float2* LZ   = Rb + 18*64;        // final LZ_q at q*64
    float2* LZB  = LZ + 256;          // ping-pong partner
    float2* Wsc  = LZB + 256;         // right chain [0,160); left chain q at 160+q*160

    const int b = blockIdx.x, t = threadIdx.x;
    const int lane = t & 31, wid = t >> 5;

    if (t < 72) {
        float phi = w[t*3+0], th = w[t*3+1], om = w[t*3+2];
        float sh,ch; sincosf(0.5f*th,&sh,&ch);
        float sa,ca; sincosf(-0.5f*(phi+om),&sa,&ca);
        float sb,cb; sincosf( 0.5f*(phi-om),&sb,&cb);
        Ush[t*4+0]=make_float2( ca*ch, sa*ch);  Ush[t*4+1]=make_float2(-cb*sh,-sb*sh);
        Ush[t*4+2]=make_float2( cb*sh,-sb*sh);  Ush[t*4+3]=make_float2( ca*ch,-sa*ch);
    }
    __syncthreads();

    // ---- closed-form site tensors (R14, verified) ----
    {
        int js[3]; int ns = 2;
        js[0] = wid; js[1] = wid + 8;
        if (wid == 0) { js[2] = 16; ns = 3; }
        if (wid == 1) { js[2] = 17; ns = 3; }
        for (int si = 0; si < ns; ++si) {
            const int j = js[si];
            const int bit = (j < 9) ? x[b*9 + j] : 0;
            const float2* U0 = Ush + j*4;
            const float2* U1 = Ush + (18+j)*4;
            const float2* U2 = Ush + (36+j)*4;
            const float2* U3 = Ush + (54+j)*4;
            float2* S = S0 + j*SSITE;
            if (j == 0) {
                if (lane < 16) {
                    const int v = lane >> 3, k = lane & 7;
                    const int k2 = k>>2, k1 = (k>>1)&1, k0 = k&1;
                    float2 e = {0,0}, f = {0,0}, g = {0,0};
                    cmac(e, U3[v*2+k2], U2[k2*2+k1]);
                    cmac(f, e, U1[k1*2+k0]);
                    cmac(g, f, U0[k0*2+bit]);
                    S[v*SST + k] = g;
                }
            } else if (j == 17) {
                if (lane < 16) {
                    const int a = lane >> 1, v = lane & 1;
                    const int a0 = a&1, a1 = (a>>1)&1, a2 = a>>2;
                    float2 v10 = U0[a0*2 + bit], v11 = U0[(1^a0)*2 + bit];
                    float2 w0={0,0}, w1={0,0};
                    cmac(w0, U1[a1*2+0],     v10); cmac(w0, U1[a1*2+1],     v11);
                    cmac(w1, U1[(1^a1)*2+0], v10); cmac(w1, U1[(1^a1)*2+1], v11);
                    float2 z0={0,0}, z1={0,0};
                    cmac(z0, U2[a2*2+0],     w0); cmac(z0, U2[a2*2+1],     w1);
                    cmac(z1, U2[(1^a2)*2+0], w0); cmac(z1, U2[(1^a2)*2+1], w1);
                    float2 f={0,0};
                    cmac(f, U3[v*2+0], z0); cmac(f, U3[v*2+1], z1);
                    S[(a*2+v)*SST] = f;
                }
            } else {
                const int r = lane >> 1, h = lane & 1;
                const int a = r >> 1, v = r & 1;
                const int a0 = a&1, a1 = (a>>1)&1, a2 = a>>2;
                float2 t0 = U3[v*2 + h];
                float2 c0={0,0}, c1={0,0};
                cmac(c0, t0, U2[(h^a2)*2 + 0]);
                cmac(c1, t0, U2[(h^a2)*2 + 1]);
                float2 d00={0,0},d01={0,0},d10={0,0},d11={0,0};
                cmac(d00, c0, U1[a1*2+0]);     cmac(d01, c0, U1[a1*2+1]);
                cmac(d10, c1, U1[(1^a1)*2+0]); cmac(d11, c1, U1[(1^a1)*2+1]);
                float2 g0 = U0[a0*2 + bit], g1 = U0[(1^a0)*2 + bit];
                float2 e00={0,0},e01={0,0},e10={0,0},e11={0,0};
                cmac(e00, d00, g0); cmac(e01, d01, g1);
                cmac(e10, d10, g0); cmac(e11, d11, g1);
                float2* Srow = S + r*SST + h*4;
                Srow[0]=e00; Srow[1]=e01; Srow[2]=e10; Srow[3]=e11;
            }
        }
    }
    __syncthreads();
    const float2* A = S0;

    // ---- right chain (warps 0-3): sites 16..5 -> Rb[5] ----
    if (wid < 4) {
        const int t4 = t;
        const int r = t4 >> 3, be2 = t4 & 7;
        const int p = t4 >> 1, s = t4 & 1;
        const int a1 = p >> 3, a2 = p & 7;

        if (t4 < 64) {
            const int i1 = t4 >> 3, i2 = t4 & 7;
            const float2* A17 = A + 17*SSITE;
            float2 acc = {0,0};
            cmacc(acc, A17[(2*i1  )*SST], A17[(2*i2  )*SST]);
            cmacc(acc, A17[(2*i1+1)*SST], A17[(2*i2+1)*SST]);
            Rb[17*64 + t4] = acc;
        }
        float4 s1r[4], s2r[4];
        {
            const float4* P1 = (const float4*)(A + 16*SSITE + r*SST);
            const float4* P2 = (const float4*)(A + 16*SSITE + (a2*2+s)*SST);
#pragma unroll
            for (int k = 0; k < 4; ++k) { s1r[k] = P1[k]; s2r[k] = P2[k]; }
        }
        asm volatile("bar.sync 1, 128;" ::: "memory");

        for (int j = 16; j >= 5; --j) {
            const float2* Rin = Rb + (j+1)*64;
            float2*       Rout= Rb + j*64;
            {
                float2 rv[8];
#pragma unroll
                for (int be = 0; be < 8; ++be) rv[be] = Rin[be*8 + be2];
                float2 A0={0,0},A1={0,0},A2={0,0},A3={0,0};
                cmac(A0, f2lo(s1r[0]), rv[0]);  cmac(A1, f2hi(s1r[0]), rv[1]);
                cmac(A2, f2lo(s1r[1]), rv[2]);  cmac(A3, f2hi(s1r[1]), rv[3]);
                cmac(A0, f2lo(s1r[2]), rv[4]);  cmac(A1, f2hi(s1r[2]), rv[5]);
                cmac(A2, f2lo(s1r[3]), rv[6]);  cmac(A3, f2hi(s1r[3]), rv[7]);
                Wsc[r*WST + be2] = make_float2(A0.x+A1.x+A2.x+A3.x,
                                               A0.y+A1.y+A2.y+A3.y);
            }
            __syncwarp();
            {
                const float4* Mr = (const float4*)(Wsc + (a1*2+s)*WST);
                float4 m0=Mr[0], m1=Mr[1], m2=Mr[2], m3=Mr[3];
                float2 B0={0,0},B1={0,0},B2={0,0},B3={0,0};
                cmacc(B0, f2lo(m0), f2lo(s2r[0]));  cmacc(B1, f2hi(m0), f2hi(s2r[0]));
                cmacc(B2, f2lo(m1), f2lo(s2r[1]));  cmacc(B3, f2hi(m1), f2hi(s2r[1]));
                cmacc(B0, f2lo(m2), f2lo(s2r[2]));  cmacc(B1, f2hi(m2), f2hi(s2r[2]));
                cmacc(B2, f2lo(m3), f2lo(s2r[3]));  cmacc(B3, f2hi(m3), f2hi(s2r[3]));
                float vx = B0.x+B1.x+B2.x+B3.x, vy = B0.y+B1.y+B2.y+B3.y;
                vx += __shfl_xor_sync(0xffffffffu, vx, 1);
                vy += __shfl_xor_sync(0xffffffffu, vy, 1);
                if (s == 0) Rout[a1*8 + a2] = make_float2(vx, vy);
            }
            if (j > 5) {
                const float4* P1 = (const float4*)(A + (j-1)*SSITE + r*SST);
                const float4* P2 = (const float4*)(A + (j-1)*SSITE + (a2*2+s)*SST);
#pragma unroll
                for (int k = 0; k < 4; ++k) { s1r[k] = P1[k]; s2r[k] = P2[k]; }
            }
            asm volatile("bar.sync 1, 128;" ::: "memory");
        }
    } else {
        // ---- left chains (warps 4-7): chain q, Z on sites 0..q, plain to bond 4.
        // Ping-pong LZ <-> LZB (4 transfers, even -> final result lands in LZ).
        const int q = wid - 4;
        float2* La = LZ  + q*64;
        float2* Lb = LZB + q*64;
        float2* Wq = Wsc + 160 + q*160;
        // Z-gram at site 0
        const int b1 = lane >> 2, b2h = lane & 3;
        float2 k0 = A[b1], k1 = A[SST + b1];
#pragma unroll
        for (int hh = 0; hh < 2; ++hh) {
            const int b2 = b2h + 4*hh;
            float2 acc = {0,0}, tq = {0,0};
            cmacc(acc, k0, A[b2]);
            cmacc(tq,  k1, A[SST + b2]);
            La[b1*8 + b2] = make_float2(acc.x - tq.x, acc.y - tq.y);
        }
        __syncwarp();
        ltrans(A + 1*SSITE, La, Lb, Wq, lane, (1 <= q) ? 1 : 0);
        ltrans(A + 2*SSITE, Lb, La, Wq, lane, (2 <= q) ? 1 : 0);
        ltrans(A + 3*SSITE, La, Lb, Wq, lane, (3 <= q) ? 1 : 0);
        ltrans(A + 4*SSITE, Lb, La, Wq, lane, 0);
    }
    __syncthreads();

    // ---- EVs: out[q] = <LZ_q@bond4, Rb[5]>   (den = 1 by unitarity) ----
    if (wid < 4) {
        float v = dot64_re(LZ + wid*64, Rb + 5*64, lane);
        if (lane == 0) out[b*4 + wid] = v;
    }
}

extern "C" void kernel_launch(void* const* d_in, const int* in_sizes, int n_in,
                              void* d_out, int out_size) {
    const float* w;
    const int*   xin;
    if (n_in >= 2 && in_sizes[0] == 4*18*3) {
        w   = (const float*)d_in[0];
        xin = (const int*)  d_in[1];
    } else {
        w   = (const float*)d_in[1];
        xin = (const int*)  d_in[0];
    }
    float* out = (float*)d_out;

    cudaFuncSetAttribute(vqc_mps_kernel,
                         cudaFuncAttributeMaxDynamicSharedMemorySize,
                         (int)SMEM_BYTES);
    vqc_mps_kernel<<<64, TPB, SMEM_BYTES>>>(w, xin, out);
}

// round 17
// speedup vs baseline: 1.0331x; 1.0331x over previous
#include <cuda_runtime.h>

#define TPB   256
#define SST   10
#define SSITE (16*SST)
#define WST   10

__device__ __forceinline__ void cmac(float2& c, float2 a, float2 b) {
    c.x = fmaf(a.x,b.x,fmaf(-a.y,b.y,c.x)); c.y = fmaf(a.x,b.y,fmaf(a.y,b.x,c.y));
}
__device__ __forceinline__ void cmacc(float2& c, float2 a, float2 b) { // a*conj(b)
    c.x = fmaf(a.x,b.x,fmaf(a.y,b.y,c.x));  c.y = fmaf(a.y,b.x,fmaf(-a.x,b.y,c.y));
}
__device__ __forceinline__ float2 f2lo(float4 v){return make_float2(v.x,v.y);}
__device__ __forceinline__ float2 f2hi(float4 v){return make_float2(v.z,v.w);}

#define F2_TOTAL (18*SSITE + 288 + 18*64 + 8*64 + 5*160)
#define SMEM_BYTES (F2_TOTAL*8)

// single-warp L transfer; zf=1 inserts Z on the physical leg.
// Lin/Lout NOT restrict (R15 lesson); always distinct buffers (ping-pong).
__device__ __forceinline__ void ltrans(const float2* __restrict__ Am,
                                       const float2* Lin,
                                       float2* Lout,
                                       float2* __restrict__ Wsc, int lane, int zf)
{
    {   const int q = lane >> 1, h = lane & 1;
        const int s = q >> 3, b2 = q & 7;
        float2 a0={0,0},a1={0,0},a2={0,0},a3={0,0};
#pragma unroll
        for (int b1 = 0; b1 < 8; ++b1) {
            float2 lv = Lin[b1*8 + b2];
            const float4* Ar = (const float4*)(Am + (b1*2+s)*SST);
            float4 w0 = Ar[2*h], w1 = Ar[2*h+1];
            cmac(a0,lv,f2lo(w0)); cmac(a1,lv,f2hi(w0));
            cmac(a2,lv,f2lo(w1)); cmac(a3,lv,f2hi(w1));
        }
        const float sg = (s && zf) ? -1.f : 1.f;
        float2* wr = Wsc + q*WST + 4*h;
        wr[0]=make_float2(sg*a0.x,sg*a0.y); wr[1]=make_float2(sg*a1.x,sg*a1.y);
        wr[2]=make_float2(sg*a2.x,sg*a2.y); wr[3]=make_float2(sg*a3.x,sg*a3.y);
    }
    __syncwarp();
    {   const int g1 = lane >> 2, g2h = lane & 3;
#pragma unroll
        for (int hh = 0; hh < 2; ++hh) {
            const int g2 = g2h + 4*hh;
            float2 p0={0,0},p1={0,0};
#pragma unroll
            for (int q = 0; q < 16; q += 2) {
                const int r0 = ((q  )&7)*2 + ((q  )>>3);
                const int r1 = ((q+1)&7)*2 + ((q+1)>>3);
                cmacc(p0, Wsc[(q  )*WST + g1], Am[r0*SST + g2]);
                cmacc(p1, Wsc[(q+1)*WST + g1], Am[r1*SST + g2]);
            }
            Lout[g1*8+g2] = make_float2(p0.x+p1.x, p0.y+p1.y);
        }
    }
    __syncwarp();
}

__device__ __forceinline__ float dot64_re(const float2* L, const float2* R, int lane) {
    float2 l0=L[lane], r0=R[lane], l1=L[lane+32], r1=R[lane+32];
    float v = l0.x*r0.x - l0.y*r0.y + l1.x*r1.x - l1.y*r1.y;
#pragma unroll
    for (int o = 16; o > 0; o >>= 1) v += __shfl_xor_sync(0xffffffffu, v, o);
    return v;
}

__global__ void __launch_bounds__(TPB, 1) vqc_mps_kernel(
    const float* __restrict__ w, const int* __restrict__ x, float* __restrict__ out)
{
    extern __shared__ float2 sm[];
    float2* S0   = sm;
    float2* Ush  = S0 + 18*SSITE;
    float2* Rb   = Ush + 288;
    float2* LZ   = Rb + 18*64;        // ping-pong A
    float2* LZB  = LZ + 256;          // ping-pong B (final LZ_q lands here)
    float2* Wsc  = LZB + 256;         // right chain [0,160); left chain q at 160+q*160

    const int b = blockIdx.x, t = threadIdx.x;
    const int lane = t & 31, wid = t >> 5;

    if (t < 72) {
        float phi = w[t*3+0], th = w[t*3+1], om = w[t*3+2];
        float sh,ch; sincosf(0.5f*th,&sh,&ch);
        float sa,ca; sincosf(-0.5f*(phi+om),&sa,&ca);
        float sb,cb; sincosf( 0.5f*(phi-om),&sb,&cb);
        Ush[t*4+0]=make_float2( ca*ch, sa*ch);  Ush[t*4+1]=make_float2(-cb*sh,-sb*sh);
        Ush[t*4+2]=make_float2( cb*sh,-sb*sh);  Ush[t*4+3]=make_float2( ca*ch,-sa*ch);
    }
    __syncthreads();

    // ---- closed-form site tensors (R14, verified) ----
    {
        int js[3]; int ns = 2;
        js[0] = wid; js[1] = wid + 8;
        if (wid == 0) { js[2] = 16; ns = 3; }
        if (wid == 1) { js[2] = 17; ns = 3; }
        for (int si = 0; si < ns; ++si) {
            const int j = js[si];
            const int bit = (j < 9) ? x[b*9 + j] : 0;
            const float2* U0 = Ush + j*4;
            const float2* U1 = Ush + (18+j)*4;
            const float2* U2 = Ush + (36+j)*4;
            const float2* U3 = Ush + (54+j)*4;
            float2* S = S0 + j*SSITE;
            if (j == 0) {
                if (lane < 16) {
                    const int v = lane >> 3, k = lane & 7;
                    const int k2 = k>>2, k1 = (k>>1)&1, k0 = k&1;
                    float2 e = {0,0}, f = {0,0}, g = {0,0};
                    cmac(e, U3[v*2+k2], U2[k2*2+k1]);
                    cmac(f, e, U1[k1*2+k0]);
                    cmac(g, f, U0[k0*2+bit]);
                    S[v*SST + k] = g;
                }
            } else if (j == 17) {
                if (lane < 16) {
                    const int a = lane >> 1, v = lane & 1;
                    const int a0 = a&1, a1 = (a>>1)&1, a2 = a>>2;
                    float2 v10 = U0[a0*2 + bit], v11 = U0[(1^a0)*2 + bit];
                    float2 w0={0,0}, w1={0,0};
                    cmac(w0, U1[a1*2+0],     v10); cmac(w0, U1[a1*2+1],     v11);
                    cmac(w1, U1[(1^a1)*2+0], v10); cmac(w1, U1[(1^a1)*2+1], v11);
                    float2 z0={0,0}, z1={0,0};
                    cmac(z0, U2[a2*2+0],     w0); cmac(z0, U2[a2*2+1],     w1);
                    cmac(z1, U2[(1^a2)*2+0], w0); cmac(z1, U2[(1^a2)*2+1], w1);
                    float2 f={0,0};
                    cmac(f, U3[v*2+0], z0); cmac(f, U3[v*2+1], z1);
                    S[(a*2+v)*SST] = f;
                }
            } else {
                const int r = lane >> 1, h = lane & 1;
                const int a = r >> 1, v = r & 1;
                const int a0 = a&1, a1 = (a>>1)&1, a2 = a>>2;
                float2 t0 = U3[v*2 + h];
                float2 c0={0,0}, c1={0,0};
                cmac(c0, t0, U2[(h^a2)*2 + 0]);
                cmac(c1, t0, U2[(h^a2)*2 + 1]);
                float2 d00={0,0},d01={0,0},d10={0,0},d11={0,0};
                cmac(d00, c0, U1[a1*2+0]);     cmac(d01, c0, U1[a1*2+1]);
                cmac(d10, c1, U1[(1^a1)*2+0]); cmac(d11, c1, U1[(1^a1)*2+1]);
                float2 g0 = U0[a0*2 + bit], g1 = U0[(1^a0)*2 + bit];
                float2 e00={0,0},e01={0,0},e10={0,0},e11={0,0};
                cmac(e00, d00, g0); cmac(e01, d01, g1);
                cmac(e10, d10, g0); cmac(e11, d11, g1);
                float2* Srow = S + r*SST + h*4;
                Srow[0]=e00; Srow[1]=e01; Srow[2]=e10; Srow[3]=e11;
            }
        }
    }
    __syncthreads();
    const float2* A = S0;

    // ---- right chain (warps 0-3): sites 16..4 -> Rb[4] ----
    if (wid < 4) {
        const int t4 = t;
        const int r = t4 >> 3, be2 = t4 & 7;
        const int p = t4 >> 1, s = t4 & 1;
        const int a1 = p >> 3, a2 = p & 7;

        if (t4 < 64) {
            const int i1 = t4 >> 3, i2 = t4 & 7;
            const float2* A17 = A + 17*SSITE;
            float2 acc = {0,0};
            cmacc(acc, A17[(2*i1  )*SST], A17[(2*i2  )*SST]);
            cmacc(acc, A17[(2*i1+1)*SST], A17[(2*i2+1)*SST]);
            Rb[17*64 + t4] = acc;
        }
        float4 s1r[4], s2r[4];
        {
            const float4* P1 = (const float4*)(A + 16*SSITE + r*SST);
            const float4* P2 = (const float4*)(A + 16*SSITE + (a2*2+s)*SST);
#pragma unroll
            for (int k = 0; k < 4; ++k) { s1r[k] = P1[k]; s2r[k] = P2[k]; }
        }
        asm volatile("bar.sync 1, 128;" ::: "memory");

        for (int j = 16; j >= 4; --j) {
            const float2* Rin = Rb + (j+1)*64;
            float2*       Rout= Rb + j*64;
            {
                float2 rv[8];
#pragma unroll
                for (int be = 0; be < 8; ++be) rv[be] = Rin[be*8 + be2];
                float2 A0={0,0},A1={0,0},A2={0,0},A3={0,0};
                cmac(A0, f2lo(s1r[0]), rv[0]);  cmac(A1, f2hi(s1r[0]), rv[1]);
                cmac(A2, f2lo(s1r[1]), rv[2]);  cmac(A3, f2hi(s1r[1]), rv[3]);
                cmac(A0, f2lo(s1r[2]), rv[4]);  cmac(A1, f2hi(s1r[2]), rv[5]);
                cmac(A2, f2lo(s1r[3]), rv[6]);  cmac(A3, f2hi(s1r[3]), rv[7]);
                Wsc[r*WST + be2] = make_float2(A0.x+A1.x+A2.x+A3.x,
                                               A0.y+A1.y+A2.y+A3.y);
            }
            __syncwarp();
            {
                const float4* Mr = (const float4*)(Wsc + (a1*2+s)*WST);
                float4 m0=Mr[0], m1=Mr[1], m2=Mr[2], m3=Mr[3];
                float2 B0={0,0},B1={0,0},B2={0,0},B3={0,0};
                cmacc(B0, f2lo(m0), f2lo(s2r[0]));  cmacc(B1, f2hi(m0), f2hi(s2r[0]));
                cmacc(B2, f2lo(m1), f2lo(s2r[1]));  cmacc(B3, f2hi(m1), f2hi(s2r[1]));
                cmacc(B0, f2lo(m2), f2lo(s2r[2]));  cmacc(B1, f2hi(m2), f2hi(s2r[2]));
                cmacc(B2, f2lo(m3), f2lo(s2r[3]));  cmacc(B3, f2hi(m3), f2hi(s2r[3]));
                float vx = B0.x+B1.x+B2.x+B3.x, vy = B0.y+B1.y+B2.y+B3.y;
                vx += __shfl_xor_sync(0xffffffffu, vx, 1);
                vy += __shfl_xor_sync(0xffffffffu, vy, 1);
                if (s == 0) Rout[a1*8 + a2] = make_float2(vx, vy);
            }
            if (j > 4) {
                const float4* P1 = (const float4*)(A + (j-1)*SSITE + r*SST);
                const float4* P2 = (const float4*)(A + (j-1)*SSITE + (a2*2+s)*SST);
#pragma unroll
                for (int k = 0; k < 4; ++k) { s1r[k] = P1[k]; s2r[k] = P2[k]; }
            }
            asm volatile("bar.sync 1, 128;" ::: "memory");
        }
    } else {
        // ---- left chains (warps 4-7): chain q, Z on sites 0..min(q,3), to bond 4.
        // gram -> LZ, 3 ltrans ping-pong: LZ -> LZB -> LZ -> LZB (final in LZB).
        const int q = wid - 4;
        float2* La = LZ  + q*64;
        float2* Lb = LZB + q*64;
        float2* Wq = Wsc + 160 + q*160;
        // Z-gram at site 0 (Z_0 present in every chain)
        const int b1 = lane >> 2, b2h = lane & 3;
        float2 k0 = A[b1], k1 = A[SST + b1];
#pragma unroll
        for (int hh = 0; hh < 2; ++hh) {
            const int b2 = b2h + 4*hh;
            float2 acc = {0,0}, tq = {0,0};
            cmacc(acc, k0, A[b2]);
            cmacc(tq,  k1, A[SST + b2]);
            La[b1*8 + b2] = make_float2(acc.x - tq.x, acc.y - tq.y);
        }
        __syncwarp();
        ltrans(A + 1*SSITE, La, Lb, Wq, lane, (1 <= q) ? 1 : 0);
        ltrans(A + 2*SSITE, Lb, La, Wq, lane, (2 <= q) ? 1 : 0);
        ltrans(A + 3*SSITE, La, Lb, Wq, lane, (3 <= q) ? 1 : 0);
    }
    __syncthreads();

    // ---- EVs: out[q] = <LZ_q@bond4 (in LZB), Rb[4]>  (den = 1 by unitarity) ----
    if (wid < 4) {
        float v = dot64_re(LZB + wid*64, Rb + 4*64, lane);
        if (lane == 0) out[b*4 + wid] = v;
    }
}

extern "C" void kernel_launch(void* const* d_in, const int* in_sizes, int n_in,
                              void* d_out, int out_size) {
    const float* w;
    const int*   xin;
    if (n_in >= 2 && in_sizes[0] == 4*18*3) {
        w   = (const float*)d_in[0];
        xin = (const int*)  d_in[1];
    } else {
        w   = (const float*)d_in[1];
        xin = (const int*)  d_in[0];
    }
    float* out = (float*)d_out;

    cudaFuncSetAttribute(vqc_mps_kernel,
                         cudaFuncAttributeMaxDynamicSharedMemorySize,
                         (int)SMEM_BYTES);
    vqc_mps_kernel<<<64, TPB, SMEM_BYTES>>>(w, xin, out);
}